// round 1
// baseline (speedup 1.0000x reference)
#include <cuda_runtime.h>
#include <cstdint>

// Problem constants
constexpr int Bv = 4, Cv = 8, Tv = 512, Fv = 512, Hh = 8, DKv = 64;
constexpr int M  = Bv * Cv * Tv;       // 16384 rows
constexpr int GN = 1024, GK = 1024;    // packed complex GEMM dims
constexpr int BM = 128, BN = 64, BK = 32;
constexpr int AST = BM + 4;            // 132, pad kills transpose-store conflicts
constexpr int BST = BN + 4;            // 68

// -------- scratch (allocation-free: __device__ globals) --------
__device__ float g_Wp[4][GN * GK];     // packed weights: q,k,v,o  (16 MB)
__device__ float g_bp[4][GN];          // packed biases
__device__ float g_Qr[M * Fv];
__device__ float g_Qi[M * Fv];
__device__ float g_Kr[M * Fv];
__device__ float g_Ki[M * Fv];
__device__ float g_Vr[M * Fv];
__device__ float g_Vi[M * Fv];
__device__ float g_Ar[M * Fv];
__device__ float g_Ai[M * Fv];

// -------- f32x2 packed math (PTX-only; ptxas never auto-fuses) --------
#define FMA2(d, a, b, c) \
    asm("fma.rn.f32x2 %0, %1, %2, %3;" : "=l"(d) : "l"(a), "l"(b), "l"(c))
#define DUP2(d, s) \
    asm("mov.b64 %0, {%1, %1};" : "=l"(d) : "r"(s))

static __device__ __forceinline__ float2 ull_as_f2(unsigned long long u) {
    float2 f;
    f.x = __uint_as_float((unsigned)(u & 0xffffffffull));
    f.y = __uint_as_float((unsigned)(u >> 32));
    return f;
}

// ============================================================================
// Pack complex weights into real block matrix:
//   Wbig[n][k]  n<512: [Wr | -Wi],  n>=512: [Wi | Wr]
//   bbig[n]     n<512: br-bi,       n>=512: br+bi
// ============================================================================
__global__ void pack_weights(const float* __restrict__ Wr, const float* __restrict__ Wi,
                             const float* __restrict__ br, const float* __restrict__ bi,
                             float* __restrict__ Wp, float* __restrict__ bp)
{
    int idx = blockIdx.x * 256 + threadIdx.x;       // 0 .. 1024*1024-1
    int n = idx >> 10, k = idx & 1023;
    float v;
    if (n < 512) {
        v = (k < 512) ? Wr[n * 512 + k] : -Wi[n * 512 + (k - 512)];
    } else {
        int nn = n - 512;
        v = (k < 512) ? Wi[nn * 512 + k] : Wr[nn * 512 + (k - 512)];
    }
    Wp[idx] = v;
    if (idx < GN) {
        bp[idx] = (idx < 512) ? (br[idx] - bi[idx]) : (br[idx - 512] + bi[idx - 512]);
    }
}

// ============================================================================
// Fused complex-linear GEMM:  Y[m][n] = sum_k X[m][k] * Wp[n][k] + bp[n]
// X's K dim is [xr | xi] (two separate arrays, row stride 512).
// Output n<512 -> Yr, n>=512 -> Yi. Optional leaky-relu epilogue.
// f32x2 packed inner loop, 128x64x32 tile, 256 threads, 8x4 micro-tile.
// ============================================================================
__global__ __launch_bounds__(256, 2)
void cgemm(const float* __restrict__ Xr, const float* __restrict__ Xi,
           const float* __restrict__ Wp, const float* __restrict__ bp,
           float* __restrict__ Yr, float* __restrict__ Yi, int do_lrelu)
{
    __shared__ float As[BK * AST];
    __shared__ float Bs[BK * BST];

    const int tid = threadIdx.x;
    const int bm  = blockIdx.x * BM;
    const int bn  = blockIdx.y * BN;
    const int tx  = tid & 15, ty = tid >> 4;
    const int m0  = ty * 8,  n0 = tx * 4;

    unsigned long long acc[4][4];
#pragma unroll
    for (int p = 0; p < 4; p++)
#pragma unroll
        for (int j = 0; j < 4; j++) acc[p][j] = 0ull;

    for (int kt = 0; kt < GK; kt += BK) {
        // ---- load A tile (128 x 32), transposed into smem ----
        const float* Asrc = (kt < 512) ? Xr : Xi;
        const int kof = kt & 511;
#pragma unroll
        for (int i = 0; i < 4; i++) {
            int idx = tid + i * 256;
            int r = idx >> 3, c4 = idx & 7;
            float4 v = *(const float4*)&Asrc[(bm + r) * 512 + kof + c4 * 4];
            As[(c4 * 4 + 0) * AST + r] = v.x;
            As[(c4 * 4 + 1) * AST + r] = v.y;
            As[(c4 * 4 + 2) * AST + r] = v.z;
            As[(c4 * 4 + 3) * AST + r] = v.w;
        }
        // ---- load B tile (64 x 32), transposed into smem ----
#pragma unroll
        for (int i = 0; i < 2; i++) {
            int idx = tid + i * 256;
            int r = idx >> 3, c4 = idx & 7;
            float4 v = *(const float4*)&Wp[(bn + r) * GK + kt + c4 * 4];
            Bs[(c4 * 4 + 0) * BST + r] = v.x;
            Bs[(c4 * 4 + 1) * BST + r] = v.y;
            Bs[(c4 * 4 + 2) * BST + r] = v.z;
            Bs[(c4 * 4 + 3) * BST + r] = v.w;
        }
        __syncthreads();

#pragma unroll 8
        for (int k = 0; k < BK; k++) {
            ulonglong2 aA = *(const ulonglong2*)&As[k * AST + m0];
            ulonglong2 aB = *(const ulonglong2*)&As[k * AST + m0 + 4];
            float4 bv = *(const float4*)&Bs[k * BST + n0];
            unsigned long long b0, b1, b2, b3;
            DUP2(b0, __float_as_uint(bv.x));
            DUP2(b1, __float_as_uint(bv.y));
            DUP2(b2, __float_as_uint(bv.z));
            DUP2(b3, __float_as_uint(bv.w));
            unsigned long long a0 = aA.x, a1 = aA.y, a2 = aB.x, a3 = aB.y;
            FMA2(acc[0][0], a0, b0, acc[0][0]);
            FMA2(acc[0][1], a0, b1, acc[0][1]);
            FMA2(acc[0][2], a0, b2, acc[0][2]);
            FMA2(acc[0][3], a0, b3, acc[0][3]);
            FMA2(acc[1][0], a1, b0, acc[1][0]);
            FMA2(acc[1][1], a1, b1, acc[1][1]);
            FMA2(acc[1][2], a1, b2, acc[1][2]);
            FMA2(acc[1][3], a1, b3, acc[1][3]);
            FMA2(acc[2][0], a2, b0, acc[2][0]);
            FMA2(acc[2][1], a2, b1, acc[2][1]);
            FMA2(acc[2][2], a2, b2, acc[2][2]);
            FMA2(acc[2][3], a2, b3, acc[2][3]);
            FMA2(acc[3][0], a3, b0, acc[3][0]);
            FMA2(acc[3][1], a3, b1, acc[3][1]);
            FMA2(acc[3][2], a3, b2, acc[3][2]);
            FMA2(acc[3][3], a3, b3, acc[3][3]);
        }
        __syncthreads();
    }

    // ---- epilogue: bias, optional lrelu, route to real/imag halves ----
    float* Yd;
    int nof;
    if (bn < 512) { Yd = Yr; nof = bn; }
    else          { Yd = Yi; nof = bn - 512; }

    float bias[4];
#pragma unroll
    for (int j = 0; j < 4; j++) bias[j] = bp[bn + n0 + j];

#pragma unroll
    for (int p = 0; p < 4; p++) {
        float4 r0, r1;
        float2 f0 = ull_as_f2(acc[p][0]);
        float2 f1 = ull_as_f2(acc[p][1]);
        float2 f2 = ull_as_f2(acc[p][2]);
        float2 f3 = ull_as_f2(acc[p][3]);
        r0.x = f0.x + bias[0]; r1.x = f0.y + bias[0];
        r0.y = f1.x + bias[1]; r1.y = f1.y + bias[1];
        r0.z = f2.x + bias[2]; r1.z = f2.y + bias[2];
        r0.w = f3.x + bias[3]; r1.w = f3.y + bias[3];
        if (do_lrelu) {
            r0.x = r0.x >= 0.f ? r0.x : 0.01f * r0.x;
            r0.y = r0.y >= 0.f ? r0.y : 0.01f * r0.y;
            r0.z = r0.z >= 0.f ? r0.z : 0.01f * r0.z;
            r0.w = r0.w >= 0.f ? r0.w : 0.01f * r0.w;
            r1.x = r1.x >= 0.f ? r1.x : 0.01f * r1.x;
            r1.y = r1.y >= 0.f ? r1.y : 0.01f * r1.y;
            r1.z = r1.z >= 0.f ? r1.z : 0.01f * r1.z;
            r1.w = r1.w >= 0.f ? r1.w : 0.01f * r1.w;
        }
        int mrow = bm + m0 + 2 * p;
        *(float4*)&Yd[(size_t)mrow * 512 + nof + n0]       = r0;
        *(float4*)&Yd[(size_t)(mrow + 1) * 512 + nof + n0] = r1;
    }
}

// ============================================================================
// Channel attention: per (b,h,t), 8x8 complex scores (no softmax), then S@V.
// grid (T=512, H=8, B=4), 128 threads. lrelu on merged output in epilogue.
// ============================================================================
__global__ void attn_kernel()
{
    __shared__ float sm[6][8][68];          // qr,qi,kr,ki,vr,vi  (padded)
    __shared__ float ssr[8][9], ssi[8][9];

    const int t = blockIdx.x, h = blockIdx.y, b = blockIdx.z;
    const int tid = threadIdx.x;

    // cooperative load: 8 channels x 64 contiguous floats per tensor
    {
        int c = tid >> 4, d4 = (tid & 15) << 2;
        size_t base = (((size_t)(b * 8 + c) * 512 + t) * 512) + h * 64 + d4;
        *(float4*)&sm[0][c][d4] = *(const float4*)&g_Qr[base];
        *(float4*)&sm[1][c][d4] = *(const float4*)&g_Qi[base];
        *(float4*)&sm[2][c][d4] = *(const float4*)&g_Kr[base];
        *(float4*)&sm[3][c][d4] = *(const float4*)&g_Ki[base];
        *(float4*)&sm[4][c][d4] = *(const float4*)&g_Vr[base];
        *(float4*)&sm[5][c][d4] = *(const float4*)&g_Vi[base];
    }
    __syncthreads();

    // scores: sr = (qr.kr^T + qi.ki^T)/8, si = (qr.ki^T - qi.kr^T)/8
    if (tid < 64) {
        int cc = tid >> 3, e = tid & 7;
        float ar = 0.f, ai = 0.f;
#pragma unroll 8
        for (int d = 0; d < 64; d++) {
            float qr = sm[0][cc][d], qi = sm[1][cc][d];
            float kr = sm[2][e][d],  ki = sm[3][e][d];
            ar = fmaf(qr, kr, fmaf(qi, ki, ar));
            ai = fmaf(qr, ki, fmaf(-qi, kr, ai));
        }
        ssr[cc][e] = ar * 0.125f;
        ssi[cc][e] = ai * 0.125f;
    }
    __syncthreads();

    // out: xr = sr@vr - si@vi,  xi = si@vr + sr@vi, then lrelu, merged layout
#pragma unroll
    for (int i = 0; i < 4; i++) {
        int idx = tid + i * 128;
        int cc = idx >> 6, d = idx & 63;
        float xr = 0.f, xi = 0.f;
#pragma unroll
        for (int e = 0; e < 8; e++) {
            float sr_ = ssr[cc][e], si_ = ssi[cc][e];
            float vr = sm[4][e][d], vi = sm[5][e][d];
            xr = fmaf(sr_, vr, fmaf(-si_, vi, xr));
            xi = fmaf(si_, vr, fmaf(sr_, vi, xi));
        }
        xr = xr >= 0.f ? xr : 0.01f * xr;
        xi = xi >= 0.f ? xi : 0.01f * xi;
        size_t ob = (((size_t)(b * 8 + cc) * 512 + t) * 512) + h * 64 + d;
        g_Ar[ob] = xr;
        g_Ai[ob] = xi;
    }
}

// ============================================================================
// Launch: pack x4 -> cgemm(q) -> cgemm(k) -> cgemm(v,lrelu) -> attn -> cgemm(o)
// ============================================================================
extern "C" void kernel_launch(void* const* d_in, const int* in_sizes, int n_in,
                              void* d_out, int out_size)
{
    const float* in[22];
    for (int i = 0; i < 22; i++) in[i] = (const float*)d_in[i];

    float *Wp, *bp, *Qr, *Qi, *Kr, *Ki, *Vr, *Vi, *Ar, *Ai;
    cudaGetSymbolAddress((void**)&Wp, g_Wp);
    cudaGetSymbolAddress((void**)&bp, g_bp);
    cudaGetSymbolAddress((void**)&Qr, g_Qr);
    cudaGetSymbolAddress((void**)&Qi, g_Qi);
    cudaGetSymbolAddress((void**)&Kr, g_Kr);
    cudaGetSymbolAddress((void**)&Ki, g_Ki);
    cudaGetSymbolAddress((void**)&Vr, g_Vr);
    cudaGetSymbolAddress((void**)&Vi, g_Vi);
    cudaGetSymbolAddress((void**)&Ar, g_Ar);
    cudaGetSymbolAddress((void**)&Ai, g_Ai);

    float* outR = (float*)d_out;
    float* outI = outR + (size_t)M * 512;

    // inputs: 6=Wq_r 7=bq_r 8=Wq_i 9=bq_i | 10..13 k | 14..17 v | 18..21 o
    pack_weights<<<4096, 256>>>(in[6],  in[8],  in[7],  in[9],  Wp + 0 * GN * GK, bp + 0 * GN);
    pack_weights<<<4096, 256>>>(in[10], in[12], in[11], in[13], Wp + 1 * GN * GK, bp + 1 * GN);
    pack_weights<<<4096, 256>>>(in[14], in[16], in[15], in[17], Wp + 2 * GN * GK, bp + 2 * GN);
    pack_weights<<<4096, 256>>>(in[18], in[20], in[19], in[21], Wp + 3 * GN * GK, bp + 3 * GN);

    dim3 ggrid(M / BM, GN / BN);   // (128, 16)
    cgemm<<<ggrid, 256>>>(in[0], in[1], Wp + 0 * GN * GK, bp + 0 * GN, Qr, Qi, 0);
    cgemm<<<ggrid, 256>>>(in[2], in[3], Wp + 1 * GN * GK, bp + 1 * GN, Kr, Ki, 0);
    cgemm<<<ggrid, 256>>>(in[4], in[5], Wp + 2 * GN * GK, bp + 2 * GN, Vr, Vi, 1);

    attn_kernel<<<dim3(Tv, Hh, Bv), 128>>>();

    cgemm<<<ggrid, 256>>>(Ar, Ai, Wp + 3 * GN * GK, bp + 3 * GN, outR, outI, 0);
}

// round 7
// speedup vs baseline: 2.1700x; 2.1700x over previous
#include <cuda_runtime.h>
#include <cuda_bf16.h>
#include <cstdint>

// ---------------- problem constants ----------------
constexpr int Mrows = 16384;          // B*C*T = 4*8*512
constexpr int GN = 1024, GK = 1024;   // packed complex GEMM dims

// GEMM tiling
constexpr int BM = 128, BN = 256, BK = 32;
constexpr int KSTEPS = GK / BK;       // 32

// smem stage layout (bytes). Rows padded to 40 bf16 = 80 B (20 words, %32=20)
// -> fragment LDS.32 bank pattern (20*r + c) mod 32 is a permutation: conflict-free.
constexpr int ROWB = 80;
constexpr int ST_AHI = 0;
constexpr int ST_ALO = ST_AHI + BM * ROWB;      // 10240
constexpr int ST_BHI = ST_ALO + BM * ROWB;      // 20480
constexpr int ST_BLO = ST_BHI + BN * ROWB;      // 40960
constexpr int STAGE  = ST_BLO + BN * ROWB;      // 61440
constexpr int SMEM_BYTES = 2 * STAGE;           // 122880

// ---------------- device scratch (allocation-free) ----------------
__device__ __nv_bfloat16 g_Xhi[3][Mrows * GK];   // q,k,v inputs, [m, 0:512]=re, [512:1024]=im
__device__ __nv_bfloat16 g_Xlo[3][Mrows * GK];
__device__ __nv_bfloat16 g_Ahi[Mrows * GK];      // attention output (o-GEMM input)
__device__ __nv_bfloat16 g_Alo[Mrows * GK];
__device__ __nv_bfloat16 g_Whi[4][GN * GK];      // packed weights hi/lo: q,k,v,o
__device__ __nv_bfloat16 g_Wlo[4][GN * GK];
__device__ float g_bp[4][GN];                    // packed biases
__device__ float g_Qr[Mrows * 512];
__device__ float g_Qi[Mrows * 512];
__device__ float g_Kr[Mrows * 512];
__device__ float g_Ki[Mrows * 512];
__device__ float g_Vr[Mrows * 512];
__device__ float g_Vi[Mrows * 512];

// ---------------- PTX helpers (family-portable only) ----------------
#define CP_ASYNC16(dst, src) \
    asm volatile("cp.async.cg.shared.global [%0], [%1], 16;" :: "r"(dst), "l"(src))
#define CP_COMMIT() asm volatile("cp.async.commit_group;")
#define CP_WAIT(n)  asm volatile("cp.async.wait_group %0;" :: "n"(n))

__device__ __forceinline__ void mma_bf16(float* d, const uint32_t* a, uint32_t b0, uint32_t b1) {
    asm volatile(
        "mma.sync.aligned.m16n8k16.row.col.f32.bf16.bf16.f32 "
        "{%0,%1,%2,%3}, {%4,%5,%6,%7}, {%8,%9}, {%0,%1,%2,%3};"
        : "+f"(d[0]), "+f"(d[1]), "+f"(d[2]), "+f"(d[3])
        : "r"(a[0]), "r"(a[1]), "r"(a[2]), "r"(a[3]), "r"(b0), "r"(b1));
}

// ============================================================================
// pack weights into complex block matrix, split into bf16 hi/lo
//   Wbig[n][k]  n<512: [Wr | -Wi],  n>=512: [Wi | Wr]
// ============================================================================
__global__ void pack_wb(const float* __restrict__ Wr, const float* __restrict__ Wi,
                        const float* __restrict__ br, const float* __restrict__ bi,
                        __nv_bfloat16* __restrict__ Whi, __nv_bfloat16* __restrict__ Wlo,
                        float* __restrict__ bp)
{
    int idx = blockIdx.x * 256 + threadIdx.x;   // over 1M
    int n = idx >> 10, k = idx & 1023;
    float v;
    if (n < 512) v = (k < 512) ? Wr[n * 512 + k] : -Wi[n * 512 + (k - 512)];
    else         v = (k < 512) ? Wi[(n - 512) * 512 + k] : Wr[(n - 512) * 512 + (k - 512)];
    __nv_bfloat16 h = __float2bfloat16(v);
    Whi[idx] = h;
    Wlo[idx] = __float2bfloat16(v - __bfloat162float(h));
    if (idx < GN)
        bp[idx] = (idx < 512) ? (br[idx] - bi[idx]) : (br[idx - 512] + bi[idx - 512]);
}

// ============================================================================
// split fp32 inputs (re|im concat along K) into bf16 hi/lo
// ============================================================================
struct alignas(8) BF4 { __nv_bfloat16 v[4]; };

__global__ void split_in(const float* __restrict__ xr, const float* __restrict__ xi,
                         __nv_bfloat16* __restrict__ hi, __nv_bfloat16* __restrict__ lo)
{
    int i4 = (blockIdx.x * 256 + threadIdx.x) * 4;   // over 16M
    int m = i4 >> 10, k = i4 & 1023;
    const float* src = (k < 512) ? (xr + (size_t)m * 512 + k)
                                 : (xi + (size_t)m * 512 + (k - 512));
    float4 v = *(const float4*)src;
    BF4 H, L;
    float a[4] = {v.x, v.y, v.z, v.w};
#pragma unroll
    for (int j = 0; j < 4; j++) {
        __nv_bfloat16 h = __float2bfloat16(a[j]);
        H.v[j] = h;
        L.v[j] = __float2bfloat16(a[j] - __bfloat162float(h));
    }
    *(BF4*)(hi + i4) = H;
    *(BF4*)(lo + i4) = L;
}

// ============================================================================
// bf16x3 GEMM on mma.sync (HMMA): Y[16384,1024] = X @ W^T + b
//   acc += Ahi*Bhi + Ahi*Blo + Alo*Bhi   (fp32 accum; error ~1e-5)
// BM=128 BN=256 BK=32, 256 threads, warp tile 64x64 (2x4 warps),
// cp.async double-buffered. Epilogue: bias + optional lrelu, route re/im half.
// ============================================================================
__global__ void __launch_bounds__(256, 1)
gemm_mma(const __nv_bfloat16* __restrict__ Ahi_g, const __nv_bfloat16* __restrict__ Alo_g,
         const __nv_bfloat16* __restrict__ Bhi_g, const __nv_bfloat16* __restrict__ Blo_g,
         const float* __restrict__ bp, float* __restrict__ Yr, float* __restrict__ Yi,
         int do_lrelu)
{
    extern __shared__ char smem[];
    const int tid = threadIdx.x;
    const int wid = tid >> 5, lane = tid & 31;
    const int wm = wid >> 2, wn = wid & 3;        // warp grid 2 x 4
    const int r = lane >> 2, c = lane & 3;
    const int bm = blockIdx.x * BM, bn = blockIdx.y * BN;

    const uint32_t sb = (uint32_t)__cvta_generic_to_shared(smem);

    float acc[4][8][4];
#pragma unroll
    for (int mi = 0; mi < 4; mi++)
#pragma unroll
        for (int nj = 0; nj < 8; nj++)
#pragma unroll
            for (int e = 0; e < 4; e++) acc[mi][nj][e] = 0.f;

    // ---- async stage loader: 12x 16B per thread ----
    auto load_stage = [&](int s, int kt) {
        uint32_t base = sb + s * STAGE;
#pragma unroll
        for (int i = 0; i < 2; i++) {
            int j = tid + i * 256;
            int row = j >> 2, ch = j & 3;
            size_t go = (size_t)(bm + row) * GK + kt + ch * 8;
            CP_ASYNC16(base + ST_AHI + row * ROWB + ch * 16, Ahi_g + go);
            CP_ASYNC16(base + ST_ALO + row * ROWB + ch * 16, Alo_g + go);
        }
#pragma unroll
        for (int i = 0; i < 4; i++) {
            int j = tid + i * 256;
            int row = j >> 2, ch = j & 3;
            size_t go = (size_t)(bn + row) * GK + kt + ch * 8;
            CP_ASYNC16(base + ST_BHI + row * ROWB + ch * 16, Bhi_g + go);
            CP_ASYNC16(base + ST_BLO + row * ROWB + ch * 16, Blo_g + go);
        }
        CP_COMMIT();
    };

    load_stage(0, 0);

    for (int s = 0; s < KSTEPS; s++) {
        if (s + 1 < KSTEPS) {
            load_stage((s + 1) & 1, (s + 1) * BK);
            CP_WAIT(1);
        } else {
            CP_WAIT(0);
        }
        __syncthreads();

        const char* st = smem + (s & 1) * STAGE;
#pragma unroll
        for (int kk = 0; kk < 2; kk++) {
            // ---- A fragments (hi & lo), 4 m-frags ----
            uint32_t ah[4][4], al[4][4];
            {
                int ab = (wm * 64 + r) * ROWB + (kk * 8 + c) * 4;
#pragma unroll
                for (int mi = 0; mi < 4; mi++) {
                    int o = ab + mi * (16 * ROWB);
                    const char* ph = st + ST_AHI + o;
                    const char* pl = st + ST_ALO + o;
                    ah[mi][0] = *(const uint32_t*)(ph);
                    ah[mi][1] = *(const uint32_t*)(ph + 8 * ROWB);
                    ah[mi][2] = *(const uint32_t*)(ph + 16);
                    ah[mi][3] = *(const uint32_t*)(ph + 8 * ROWB + 16);
                    al[mi][0] = *(const uint32_t*)(pl);
                    al[mi][1] = *(const uint32_t*)(pl + 8 * ROWB);
                    al[mi][2] = *(const uint32_t*)(pl + 16);
                    al[mi][3] = *(const uint32_t*)(pl + 8 * ROWB + 16);
                }
            }
            // ---- B fragments per n-frag, 3 products each ----
#pragma unroll
            for (int nj = 0; nj < 8; nj++) {
                int bb = (wn * 64 + nj * 8 + r) * ROWB + (kk * 8 + c) * 4;
                const char* ph = st + ST_BHI + bb;
                const char* pl = st + ST_BLO + bb;
                uint32_t bh0 = *(const uint32_t*)(ph);
                uint32_t bh1 = *(const uint32_t*)(ph + 16);
                uint32_t bl0 = *(const uint32_t*)(pl);
                uint32_t bl1 = *(const uint32_t*)(pl + 16);
#pragma unroll
                for (int mi = 0; mi < 4; mi++) {
                    mma_bf16(acc[mi][nj], ah[mi], bh0, bh1);
                    mma_bf16(acc[mi][nj], ah[mi], bl0, bl1);
                    mma_bf16(acc[mi][nj], al[mi], bh0, bh1);
                }
            }
        }
        __syncthreads();
    }

    // ---- epilogue: bias, optional lrelu, route to re/im half ----
    float* Yd = (bn < 512) ? Yr : Yi;
    const int nsub = (bn < 512) ? 0 : 512;
#pragma unroll
    for (int mi = 0; mi < 4; mi++) {
#pragma unroll
        for (int nj = 0; nj < 8; nj++) {
            int ncol = bn + wn * 64 + nj * 8 + 2 * c;
            float b0 = bp[ncol], b1 = bp[ncol + 1];
            int row0 = bm + wm * 64 + mi * 16 + r;
#pragma unroll
            for (int hrow = 0; hrow < 2; hrow++) {
                float v0 = acc[mi][nj][2 * hrow + 0] + b0;
                float v1 = acc[mi][nj][2 * hrow + 1] + b1;
                if (do_lrelu) {
                    v0 = v0 >= 0.f ? v0 : 0.01f * v0;
                    v1 = v1 >= 0.f ? v1 : 0.01f * v1;
                }
                float2 o = make_float2(v0, v1);
                *(float2*)&Yd[(size_t)(row0 + 8 * hrow) * 512 + (ncol - nsub)] = o;
            }
        }
    }
}

// ============================================================================
// channel attention: per (b,h,t) 8x8 complex scores (no softmax), S@V, lrelu,
// write merged-head output directly as bf16 hi/lo into the o-GEMM input layout
// ============================================================================
__global__ void attn_kernel()
{
    __shared__ float sm[6][8][68];
    __shared__ float ssr[8][9], ssi[8][9];

    const int t = blockIdx.x, h = blockIdx.y, b = blockIdx.z;
    const int tid = threadIdx.x;

    {
        int c = tid >> 4, d4 = (tid & 15) << 2;
        size_t base = (((size_t)(b * 8 + c) * 512 + t) * 512) + h * 64 + d4;
        *(float4*)&sm[0][c][d4] = *(const float4*)&g_Qr[base];
        *(float4*)&sm[1][c][d4] = *(const float4*)&g_Qi[base];
        *(float4*)&sm[2][c][d4] = *(const float4*)&g_Kr[base];
        *(float4*)&sm[3][c][d4] = *(const float4*)&g_Ki[base];
        *(float4*)&sm[4][c][d4] = *(const float4*)&g_Vr[base];
        *(float4*)&sm[5][c][d4] = *(const float4*)&g_Vi[base];
    }
    __syncthreads();

    if (tid < 64) {
        int cc = tid >> 3, e = tid & 7;
        float ar = 0.f, ai = 0.f;
#pragma unroll 8
        for (int d = 0; d < 64; d++) {
            float qr = sm[0][cc][d], qi = sm[1][cc][d];
            float kr = sm[2][e][d],  ki = sm[3][e][d];
            ar = fmaf(qr, kr, fmaf(qi, ki, ar));
            ai = fmaf(qr, ki, fmaf(-qi, kr, ai));
        }
        ssr[cc][e] = ar * 0.125f;
        ssi[cc][e] = ai * 0.125f;
    }
    __syncthreads();

#pragma unroll
    for (int i = 0; i < 4; i++) {
        int idx = tid + i * 128;
        int cc = idx >> 6, d = idx & 63;
        float xr = 0.f, xi = 0.f;
#pragma unroll
        for (int e = 0; e < 8; e++) {
            float sr_ = ssr[cc][e], si_ = ssi[cc][e];
            float vr = sm[4][e][d], vi = sm[5][e][d];
            xr = fmaf(sr_, vr, fmaf(-si_, vi, xr));
            xi = fmaf(si_, vr, fmaf(sr_, vi, xi));
        }
        xr = xr >= 0.f ? xr : 0.01f * xr;
        xi = xi >= 0.f ? xi : 0.01f * xi;
        size_t mrow = (size_t)(b * 8 + cc) * 512 + t;
        size_t pr = mrow * 1024 + h * 64 + d;        // real half (k < 512)
        size_t pi = pr + 512;                         // imag half
        __nv_bfloat16 hr = __float2bfloat16(xr);
        __nv_bfloat16 hii = __float2bfloat16(xi);
        g_Ahi[pr] = hr;
        g_Alo[pr] = __float2bfloat16(xr - __bfloat162float(hr));
        g_Ahi[pi] = hii;
        g_Alo[pi] = __float2bfloat16(xi - __bfloat162float(hii));
    }
}

// ============================================================================
// host side: pack x4, split x3, gemm(q,k,v), attn, gemm(o)
// ============================================================================
extern "C" void kernel_launch(void* const* d_in, const int* in_sizes, int n_in,
                              void* d_out, int out_size)
{
    const float* in[22];
    for (int i = 0; i < 22; i++) in[i] = (const float*)d_in[i];

    void *Xhi, *Xlo, *Ahi, *Alo, *Whi, *Wlo, *bp_, *Qr, *Qi, *Kr, *Ki, *Vr, *Vi;
    cudaGetSymbolAddress(&Xhi, g_Xhi);
    cudaGetSymbolAddress(&Xlo, g_Xlo);
    cudaGetSymbolAddress(&Ahi, g_Ahi);
    cudaGetSymbolAddress(&Alo, g_Alo);
    cudaGetSymbolAddress(&Whi, g_Whi);
    cudaGetSymbolAddress(&Wlo, g_Wlo);
    cudaGetSymbolAddress(&bp_, g_bp);
    cudaGetSymbolAddress(&Qr, g_Qr);
    cudaGetSymbolAddress(&Qi, g_Qi);
    cudaGetSymbolAddress(&Kr, g_Kr);
    cudaGetSymbolAddress(&Ki, g_Ki);
    cudaGetSymbolAddress(&Vr, g_Vr);
    cudaGetSymbolAddress(&Vi, g_Vi);

    __nv_bfloat16* xhi = (__nv_bfloat16*)Xhi;
    __nv_bfloat16* xlo = (__nv_bfloat16*)Xlo;
    __nv_bfloat16* whi = (__nv_bfloat16*)Whi;
    __nv_bfloat16* wlo = (__nv_bfloat16*)Wlo;
    const size_t XSZ = (size_t)Mrows * GK;
    const size_t WSZ = (size_t)GN * GK;

    cudaFuncSetAttribute(gemm_mma, cudaFuncAttributeMaxDynamicSharedMemorySize, SMEM_BYTES);

    float* bp = (float*)bp_;
    // pack + split weights: inputs 6=Wq_r 7=bq_r 8=Wq_i 9=bq_i | 10..13 k | 14..17 v | 18..21 o
    pack_wb<<<4096, 256>>>(in[6],  in[8],  in[7],  in[9],  whi + 0 * WSZ, wlo + 0 * WSZ, bp + 0 * GN);
    pack_wb<<<4096, 256>>>(in[10], in[12], in[11], in[13], whi + 1 * WSZ, wlo + 1 * WSZ, bp + 1 * GN);
    pack_wb<<<4096, 256>>>(in[14], in[16], in[15], in[17], whi + 2 * WSZ, wlo + 2 * WSZ, bp + 2 * GN);
    pack_wb<<<4096, 256>>>(in[18], in[20], in[19], in[21], whi + 3 * WSZ, wlo + 3 * WSZ, bp + 3 * GN);

    // split activations (q, k, v)
    split_in<<<16384, 256>>>(in[0], in[1], xhi + 0 * XSZ, xlo + 0 * XSZ);
    split_in<<<16384, 256>>>(in[2], in[3], xhi + 1 * XSZ, xlo + 1 * XSZ);
    split_in<<<16384, 256>>>(in[4], in[5], xhi + 2 * XSZ, xlo + 2 * XSZ);

    dim3 gg(Mrows / BM, GN / BN);   // (128, 4)

    gemm_mma<<<gg, 256, SMEM_BYTES>>>(xhi + 0 * XSZ, xlo + 0 * XSZ, whi + 0 * WSZ, wlo + 0 * WSZ,
                                      bp + 0 * GN, (float*)Qr, (float*)Qi, 0);
    gemm_mma<<<gg, 256, SMEM_BYTES>>>(xhi + 1 * XSZ, xlo + 1 * XSZ, whi + 1 * WSZ, wlo + 1 * WSZ,
                                      bp + 1 * GN, (float*)Kr, (float*)Ki, 0);
    gemm_mma<<<gg, 256, SMEM_BYTES>>>(xhi + 2 * XSZ, xlo + 2 * XSZ, whi + 2 * WSZ, wlo + 2 * WSZ,
                                      bp + 2 * GN, (float*)Vr, (float*)Vi, 1);

    attn_kernel<<<dim3(512, 8, 4), 128>>>();

    float* outR = (float*)d_out;
    float* outI = outR + (size_t)Mrows * 512;
    gemm_mma<<<gg, 256, SMEM_BYTES>>>((__nv_bfloat16*)Ahi, (__nv_bfloat16*)Alo,
                                      whi + 3 * WSZ, wlo + 3 * WSZ,
                                      bp + 3 * GN, outR, outI, 0);
}

// round 8
// speedup vs baseline: 2.1961x; 1.0121x over previous
#include <cuda_runtime.h>
#include <cuda_bf16.h>
#include <cstdint>

// ---------------- problem constants ----------------
constexpr int Mrows = 16384;          // B*C*T = 4*8*512
constexpr int GN = 1024, GK = 1024;   // packed complex GEMM dims

// GEMM tiling
constexpr int BM = 128, BN = 256, BK = 32;
constexpr int KSTEPS = GK / BK;       // 32

// smem stage layout (bytes). Rows padded to 40 bf16 = 80 B (20 words).
// 8-row ldmatrix phases: word starts (20*r) mod 32 = 0,20,8,28,16,4,24,12
// -> disjoint 4-bank quads, conflict-free.
constexpr int ROWB = 80;
constexpr int ST_AHI = 0;
constexpr int ST_ALO = ST_AHI + BM * ROWB;      // 10240
constexpr int ST_BHI = ST_ALO + BM * ROWB;      // 20480
constexpr int ST_BLO = ST_BHI + BN * ROWB;      // 40960
constexpr int STAGE  = ST_BLO + BN * ROWB;      // 61440
constexpr int SMEM_BYTES = 2 * STAGE;           // 122880

// ---------------- device scratch (allocation-free) ----------------
__device__ __nv_bfloat16 g_Xhi[3][Mrows * GK];   // q,k,v inputs, [m, 0:512]=re, [512:1024]=im
__device__ __nv_bfloat16 g_Xlo[3][Mrows * GK];
__device__ __nv_bfloat16 g_Ahi[Mrows * GK];      // attention output (o-GEMM input)
__device__ __nv_bfloat16 g_Alo[Mrows * GK];
__device__ __nv_bfloat16 g_Whi[4][GN * GK];      // packed weights hi/lo: q,k,v,o
__device__ __nv_bfloat16 g_Wlo[4][GN * GK];
__device__ float g_bp[4][GN];                    // packed biases
__device__ float g_Qr[Mrows * 512];
__device__ float g_Qi[Mrows * 512];
__device__ float g_Kr[Mrows * 512];
__device__ float g_Ki[Mrows * 512];
__device__ float g_Vr[Mrows * 512];
__device__ float g_Vi[Mrows * 512];

// ---------------- PTX helpers (family-portable only) ----------------
#define CP_ASYNC16(dst, src) \
    asm volatile("cp.async.cg.shared.global [%0], [%1], 16;" :: "r"(dst), "l"(src))
#define CP_COMMIT() asm volatile("cp.async.commit_group;")
#define CP_WAIT(n)  asm volatile("cp.async.wait_group %0;" :: "n"(n))

#define LDSM_X4(r0, r1, r2, r3, addr) \
    asm volatile("ldmatrix.sync.aligned.m8n8.x4.shared.b16 {%0,%1,%2,%3}, [%4];" \
        : "=r"(r0), "=r"(r1), "=r"(r2), "=r"(r3) : "r"(addr))

__device__ __forceinline__ void mma_bf16(float* d, const uint32_t* a, uint32_t b0, uint32_t b1) {
    asm volatile(
        "mma.sync.aligned.m16n8k16.row.col.f32.bf16.bf16.f32 "
        "{%0,%1,%2,%3}, {%4,%5,%6,%7}, {%8,%9}, {%0,%1,%2,%3};"
        : "+f"(d[0]), "+f"(d[1]), "+f"(d[2]), "+f"(d[3])
        : "r"(a[0]), "r"(a[1]), "r"(a[2]), "r"(a[3]), "r"(b0), "r"(b1));
}

// ============================================================================
// pack weights into complex block matrix, split into bf16 hi/lo
//   Wbig[n][k]  n<512: [Wr | -Wi],  n>=512: [Wi | Wr]
// ============================================================================
__global__ void pack_wb(const float* __restrict__ Wr, const float* __restrict__ Wi,
                        const float* __restrict__ br, const float* __restrict__ bi,
                        __nv_bfloat16* __restrict__ Whi, __nv_bfloat16* __restrict__ Wlo,
                        float* __restrict__ bp)
{
    int idx = blockIdx.x * 256 + threadIdx.x;   // over 1M
    int n = idx >> 10, k = idx & 1023;
    float v;
    if (n < 512) v = (k < 512) ? Wr[n * 512 + k] : -Wi[n * 512 + (k - 512)];
    else         v = (k < 512) ? Wi[(n - 512) * 512 + k] : Wr[(n - 512) * 512 + (k - 512)];
    __nv_bfloat16 h = __float2bfloat16(v);
    Whi[idx] = h;
    Wlo[idx] = __float2bfloat16(v - __bfloat162float(h));
    if (idx < GN)
        bp[idx] = (idx < 512) ? (br[idx] - bi[idx]) : (br[idx - 512] + bi[idx - 512]);
}

// ============================================================================
// split fp32 inputs (re|im concat along K) into bf16 hi/lo
// ============================================================================
struct alignas(8) BF4 { __nv_bfloat16 v[4]; };

__global__ void split_in(const float* __restrict__ xr, const float* __restrict__ xi,
                         __nv_bfloat16* __restrict__ hi, __nv_bfloat16* __restrict__ lo)
{
    int i4 = (blockIdx.x * 256 + threadIdx.x) * 4;   // over 16M
    int m = i4 >> 10, k = i4 & 1023;
    const float* src = (k < 512) ? (xr + (size_t)m * 512 + k)
                                 : (xi + (size_t)m * 512 + (k - 512));
    float4 v = *(const float4*)src;
    BF4 H, L;
    float a[4] = {v.x, v.y, v.z, v.w};
#pragma unroll
    for (int j = 0; j < 4; j++) {
        __nv_bfloat16 h = __float2bfloat16(a[j]);
        H.v[j] = h;
        L.v[j] = __float2bfloat16(a[j] - __bfloat162float(h));
    }
    *(BF4*)(hi + i4) = H;
    *(BF4*)(lo + i4) = L;
}

// ============================================================================
// bf16x3 GEMM on mma.sync (HMMA): Y[16384,1024] = X @ W^T + b
//   acc += Ahi*Bhi + Ahi*Blo + Alo*Bhi   (fp32 accum; error ~1e-5)
// BM=128 BN=256 BK=32, 512 threads (4x4 warp grid), warp tile 32x64,
// ldmatrix.x4 fragment loads, cp.async double-buffered.
// ============================================================================
__global__ void __launch_bounds__(512, 1)
gemm_mma(const __nv_bfloat16* __restrict__ Ahi_g, const __nv_bfloat16* __restrict__ Alo_g,
         const __nv_bfloat16* __restrict__ Bhi_g, const __nv_bfloat16* __restrict__ Blo_g,
         const float* __restrict__ bp, float* __restrict__ Yr, float* __restrict__ Yi,
         int do_lrelu)
{
    extern __shared__ char smem[];
    const int tid = threadIdx.x;
    const int wid = tid >> 5, lane = tid & 31;
    const int wm = wid >> 2, wn = wid & 3;        // warp grid 4 x 4, tile 32 x 64
    const int r = lane >> 2, c = lane & 3;
    const int bm = blockIdx.x * BM, bn = blockIdx.y * BN;

    const uint32_t sb = (uint32_t)__cvta_generic_to_shared(smem);

    // ldmatrix per-lane offsets (bytes within a stage)
    // A x4: mat0 m0-7/k0, mat1 m8-15/k0, mat2 m0-7/k8, mat3 m8-15/k8
    const int arow = (lane & 7) + ((lane >> 3) & 1) * 8;
    const int akof = ((lane >> 4) & 1) * 16;
    const uint32_t a_off = (uint32_t)((wm * 32 + arow) * ROWB + akof);
    // B x4: mat0 n0-7/k0, mat1 n0-7/k8, mat2 n8-15/k0, mat3 n8-15/k8
    const int brow = (lane & 7) + ((lane >> 4) & 1) * 8;
    const int bkof = ((lane >> 3) & 1) * 16;
    const uint32_t b_off = (uint32_t)((wn * 64 + brow) * ROWB + bkof);

    float acc[2][8][4];
#pragma unroll
    for (int mi = 0; mi < 2; mi++)
#pragma unroll
        for (int nj = 0; nj < 8; nj++)
#pragma unroll
            for (int e = 0; e < 4; e++) acc[mi][nj][e] = 0.f;

    // ---- async stage loader: 6x 16B per thread ----
    auto load_stage = [&](int s, int kt) {
        uint32_t base = sb + s * STAGE;
        {
            int row = tid >> 2, ch = tid & 3;
            size_t go = (size_t)(bm + row) * GK + kt + ch * 8;
            CP_ASYNC16(base + ST_AHI + row * ROWB + ch * 16, Ahi_g + go);
            CP_ASYNC16(base + ST_ALO + row * ROWB + ch * 16, Alo_g + go);
        }
#pragma unroll
        for (int i = 0; i < 2; i++) {
            int j = tid + i * 512;
            int row = j >> 2, ch = j & 3;
            size_t go = (size_t)(bn + row) * GK + kt + ch * 8;
            CP_ASYNC16(base + ST_BHI + row * ROWB + ch * 16, Bhi_g + go);
            CP_ASYNC16(base + ST_BLO + row * ROWB + ch * 16, Blo_g + go);
        }
        CP_COMMIT();
    };

    load_stage(0, 0);

    for (int s = 0; s < KSTEPS; s++) {
        if (s + 1 < KSTEPS) {
            load_stage((s + 1) & 1, (s + 1) * BK);
            CP_WAIT(1);
        } else {
            CP_WAIT(0);
        }
        __syncthreads();

        const uint32_t stb = sb + (s & 1) * STAGE;
#pragma unroll
        for (int kk = 0; kk < 2; kk++) {
            const uint32_t kb = stb + kk * 32;
            // ---- A fragments (hi & lo), 2 m-frags, ldmatrix.x4 each ----
            uint32_t ah[2][4], al[2][4];
#pragma unroll
            for (int mi = 0; mi < 2; mi++) {
                LDSM_X4(ah[mi][0], ah[mi][1], ah[mi][2], ah[mi][3],
                        kb + ST_AHI + a_off + mi * (16 * ROWB));
                LDSM_X4(al[mi][0], al[mi][1], al[mi][2], al[mi][3],
                        kb + ST_ALO + a_off + mi * (16 * ROWB));
            }
            // ---- B fragments: 4 groups of 16 n, hi & lo ----
#pragma unroll
            for (int g = 0; g < 4; g++) {
                uint32_t bh[4], bl[4];
                LDSM_X4(bh[0], bh[1], bh[2], bh[3], kb + ST_BHI + b_off + g * (16 * ROWB));
                LDSM_X4(bl[0], bl[1], bl[2], bl[3], kb + ST_BLO + b_off + g * (16 * ROWB));
#pragma unroll
                for (int mi = 0; mi < 2; mi++) {
                    mma_bf16(acc[mi][2 * g + 0], ah[mi], bh[0], bh[1]);
                    mma_bf16(acc[mi][2 * g + 0], ah[mi], bl[0], bl[1]);
                    mma_bf16(acc[mi][2 * g + 0], al[mi], bh[0], bh[1]);
                    mma_bf16(acc[mi][2 * g + 1], ah[mi], bh[2], bh[3]);
                    mma_bf16(acc[mi][2 * g + 1], ah[mi], bl[2], bl[3]);
                    mma_bf16(acc[mi][2 * g + 1], al[mi], bh[2], bh[3]);
                }
            }
        }
        __syncthreads();
    }

    // ---- epilogue: bias, optional lrelu, route to re/im half ----
    float* Yd = (bn < 512) ? Yr : Yi;
    const int nsub = (bn < 512) ? 0 : 512;
#pragma unroll
    for (int mi = 0; mi < 2; mi++) {
#pragma unroll
        for (int nj = 0; nj < 8; nj++) {
            int ncol = bn + wn * 64 + nj * 8 + 2 * c;
            float b0 = bp[ncol], b1 = bp[ncol + 1];
            int row0 = bm + wm * 32 + mi * 16 + r;
#pragma unroll
            for (int hrow = 0; hrow < 2; hrow++) {
                float v0 = acc[mi][nj][2 * hrow + 0] + b0;
                float v1 = acc[mi][nj][2 * hrow + 1] + b1;
                if (do_lrelu) {
                    v0 = v0 >= 0.f ? v0 : 0.01f * v0;
                    v1 = v1 >= 0.f ? v1 : 0.01f * v1;
                }
                float2 o = make_float2(v0, v1);
                *(float2*)&Yd[(size_t)(row0 + 8 * hrow) * 512 + (ncol - nsub)] = o;
            }
        }
    }
}

// ============================================================================
// channel attention: per (b,h,t) 8x8 complex scores (no softmax), S@V, lrelu,
// write merged-head output directly as bf16 hi/lo into the o-GEMM input layout
// ============================================================================
__global__ void attn_kernel()
{
    __shared__ float sm[6][8][68];
    __shared__ float ssr[8][9], ssi[8][9];

    const int t = blockIdx.x, h = blockIdx.y, b = blockIdx.z;
    const int tid = threadIdx.x;

    {
        int c = tid >> 4, d4 = (tid & 15) << 2;
        size_t base = (((size_t)(b * 8 + c) * 512 + t) * 512) + h * 64 + d4;
        *(float4*)&sm[0][c][d4] = *(const float4*)&g_Qr[base];
        *(float4*)&sm[1][c][d4] = *(const float4*)&g_Qi[base];
        *(float4*)&sm[2][c][d4] = *(const float4*)&g_Kr[base];
        *(float4*)&sm[3][c][d4] = *(const float4*)&g_Ki[base];
        *(float4*)&sm[4][c][d4] = *(const float4*)&g_Vr[base];
        *(float4*)&sm[5][c][d4] = *(const float4*)&g_Vi[base];
    }
    __syncthreads();

    if (tid < 64) {
        int cc = tid >> 3, e = tid & 7;
        float ar = 0.f, ai = 0.f;
#pragma unroll 8
        for (int d = 0; d < 64; d++) {
            float qr = sm[0][cc][d], qi = sm[1][cc][d];
            float kr = sm[2][e][d],  ki = sm[3][e][d];
            ar = fmaf(qr, kr, fmaf(qi, ki, ar));
            ai = fmaf(qr, ki, fmaf(-qi, kr, ai));
        }
        ssr[cc][e] = ar * 0.125f;
        ssi[cc][e] = ai * 0.125f;
    }
    __syncthreads();

#pragma unroll
    for (int i = 0; i < 4; i++) {
        int idx = tid + i * 128;
        int cc = idx >> 6, d = idx & 63;
        float xr = 0.f, xi = 0.f;
#pragma unroll
        for (int e = 0; e < 8; e++) {
            float sr_ = ssr[cc][e], si_ = ssi[cc][e];
            float vr = sm[4][e][d], vi = sm[5][e][d];
            xr = fmaf(sr_, vr, fmaf(-si_, vi, xr));
            xi = fmaf(si_, vr, fmaf(sr_, vi, xi));
        }
        xr = xr >= 0.f ? xr : 0.01f * xr;
        xi = xi >= 0.f ? xi : 0.01f * xi;
        size_t mrow = (size_t)(b * 8 + cc) * 512 + t;
        size_t pr = mrow * 1024 + h * 64 + d;        // real half (k < 512)
        size_t pi = pr + 512;                         // imag half
        __nv_bfloat16 hr = __float2bfloat16(xr);
        __nv_bfloat16 hii = __float2bfloat16(xi);
        g_Ahi[pr] = hr;
        g_Alo[pr] = __float2bfloat16(xr - __bfloat162float(hr));
        g_Ahi[pi] = hii;
        g_Alo[pi] = __float2bfloat16(xi - __bfloat162float(hii));
    }
}

// ============================================================================
// host side: pack x4, split x3, gemm(q,k,v), attn, gemm(o)
// ============================================================================
extern "C" void kernel_launch(void* const* d_in, const int* in_sizes, int n_in,
                              void* d_out, int out_size)
{
    const float* in[22];
    for (int i = 0; i < 22; i++) in[i] = (const float*)d_in[i];

    void *Xhi, *Xlo, *Ahi, *Alo, *Whi, *Wlo, *bp_, *Qr, *Qi, *Kr, *Ki, *Vr, *Vi;
    cudaGetSymbolAddress(&Xhi, g_Xhi);
    cudaGetSymbolAddress(&Xlo, g_Xlo);
    cudaGetSymbolAddress(&Ahi, g_Ahi);
    cudaGetSymbolAddress(&Alo, g_Alo);
    cudaGetSymbolAddress(&Whi, g_Whi);
    cudaGetSymbolAddress(&Wlo, g_Wlo);
    cudaGetSymbolAddress(&bp_, g_bp);
    cudaGetSymbolAddress(&Qr, g_Qr);
    cudaGetSymbolAddress(&Qi, g_Qi);
    cudaGetSymbolAddress(&Kr, g_Kr);
    cudaGetSymbolAddress(&Ki, g_Ki);
    cudaGetSymbolAddress(&Vr, g_Vr);
    cudaGetSymbolAddress(&Vi, g_Vi);

    __nv_bfloat16* xhi = (__nv_bfloat16*)Xhi;
    __nv_bfloat16* xlo = (__nv_bfloat16*)Xlo;
    __nv_bfloat16* whi = (__nv_bfloat16*)Whi;
    __nv_bfloat16* wlo = (__nv_bfloat16*)Wlo;
    const size_t XSZ = (size_t)Mrows * GK;
    const size_t WSZ = (size_t)GN * GK;

    cudaFuncSetAttribute(gemm_mma, cudaFuncAttributeMaxDynamicSharedMemorySize, SMEM_BYTES);

    float* bp = (float*)bp_;
    // pack + split weights: inputs 6=Wq_r 7=bq_r 8=Wq_i 9=bq_i | 10..13 k | 14..17 v | 18..21 o
    pack_wb<<<4096, 256>>>(in[6],  in[8],  in[7],  in[9],  whi + 0 * WSZ, wlo + 0 * WSZ, bp + 0 * GN);
    pack_wb<<<4096, 256>>>(in[10], in[12], in[11], in[13], whi + 1 * WSZ, wlo + 1 * WSZ, bp + 1 * GN);
    pack_wb<<<4096, 256>>>(in[14], in[16], in[15], in[17], whi + 2 * WSZ, wlo + 2 * WSZ, bp + 2 * GN);
    pack_wb<<<4096, 256>>>(in[18], in[20], in[19], in[21], whi + 3 * WSZ, wlo + 3 * WSZ, bp + 3 * GN);

    // split activations (q, k, v)
    split_in<<<16384, 256>>>(in[0], in[1], xhi + 0 * XSZ, xlo + 0 * XSZ);
    split_in<<<16384, 256>>>(in[2], in[3], xhi + 1 * XSZ, xlo + 1 * XSZ);
    split_in<<<16384, 256>>>(in[4], in[5], xhi + 2 * XSZ, xlo + 2 * XSZ);

    dim3 gg(Mrows / BM, GN / BN);   // (128, 4)

    gemm_mma<<<gg, 512, SMEM_BYTES>>>(xhi + 0 * XSZ, xlo + 0 * XSZ, whi + 0 * WSZ, wlo + 0 * WSZ,
                                      bp + 0 * GN, (float*)Qr, (float*)Qi, 0);
    gemm_mma<<<gg, 512, SMEM_BYTES>>>(xhi + 1 * XSZ, xlo + 1 * XSZ, whi + 1 * WSZ, wlo + 1 * WSZ,
                                      bp + 1 * GN, (float*)Kr, (float*)Ki, 0);
    gemm_mma<<<gg, 512, SMEM_BYTES>>>(xhi + 2 * XSZ, xlo + 2 * XSZ, whi + 2 * WSZ, wlo + 2 * WSZ,
                                      bp + 2 * GN, (float*)Vr, (float*)Vi, 1);

    attn_kernel<<<dim3(512, 8, 4), 128>>>();

    float* outR = (float*)d_out;
    float* outI = outR + (size_t)Mrows * 512;
    gemm_mma<<<gg, 512, SMEM_BYTES>>>((__nv_bfloat16*)Ahi, (__nv_bfloat16*)Alo,
                                      whi + 3 * WSZ, wlo + 3 * WSZ,
                                      bp + 3 * GN, outR, outI, 0);
}